// round 15
// baseline (speedup 1.0000x reference)
#include <cuda_runtime.h>
#include <cstdint>

typedef unsigned int u32;

#define NB 1024
#define LN_EPS 1e-5f
#define ISCALE 0.0625f
#define NT 512

// SMEM byte offsets. Rows hold [hi-plane | lo-plane] packed bf16, 16B chunks
// swizzled by (chunk ^ (row & 7)) for conflict-free ldmatrix.
#define H1O 0          // h1: 64 rows x 1024B (hi 512 | lo 512)
#define H2O 65536      // h2: 128 rows x 1024B
#define IRO 196608     // I : 64 rows x 512B  (hi 256 | lo 256)
#define SMEM_BYTES 229376

__device__ __forceinline__ u32 smem_u32(const void* p) {
    u32 a;
    asm("{ .reg .u64 t; cvta.to.shared.u64 t, %1; cvt.u32.u64 %0, t; }" : "=r"(a) : "l"(p));
    return a;
}
__device__ __forceinline__ void split2(float x, float y, u32& hp, u32& lp) {
    asm("cvt.rn.bf16x2.f32 %0, %1, %2;" : "=r"(hp) : "f"(y), "f"(x));
    float hx = __uint_as_float(hp << 16);
    float hy = __uint_as_float(hp & 0xFFFF0000u);
    asm("cvt.rn.bf16x2.f32 %0, %1, %2;" : "=r"(lp) : "f"(y - hy), "f"(x - hx));
}
__device__ __forceinline__ void mma16816(float* c, const u32* a, const u32* b) {
    asm volatile(
        "mma.sync.aligned.m16n8k16.row.col.f32.bf16.bf16.f32 "
        "{%0,%1,%2,%3}, {%4,%5,%6,%7}, {%8,%9}, {%0,%1,%2,%3};"
        : "+f"(c[0]), "+f"(c[1]), "+f"(c[2]), "+f"(c[3])
        : "r"(a[0]), "r"(a[1]), "r"(a[2]), "r"(a[3]), "r"(b[0]), "r"(b[1]));
}
__device__ __forceinline__ void mma3(float* c, const u32* aH, const u32* aL,
                                     const u32* bH, const u32* bL) {
    mma16816(c, aH, bH);
    mma16816(c, aL, bH);
    mma16816(c, aH, bL);
}
__device__ __forceinline__ void ldm4(u32* r, u32 a) {
    asm volatile("ldmatrix.sync.aligned.m8n8.x4.shared.b16 {%0,%1,%2,%3}, [%4];"
        : "=r"(r[0]), "=r"(r[1]), "=r"(r[2]), "=r"(r[3]) : "r"(a));
}
__device__ __forceinline__ void ldm4t(u32* r, u32 a) {
    asm volatile("ldmatrix.sync.aligned.m8n8.x4.trans.shared.b16 {%0,%1,%2,%3}, [%4];"
        : "=r"(r[0]), "=r"(r[1]), "=r"(r[2]), "=r"(r[3]) : "r"(a));
}
// store one float4 as split hi/lo planes at (row, d0) with row stride rs bytes, plane gap pg
__device__ __forceinline__ void plane_st(char* bp, int row, int d0, int rs, int pg, float4 v) {
    u32 h01, l01, h23, l23;
    split2(v.x, v.y, h01, l01);
    split2(v.z, v.w, h23, l23);
    char* p = bp + row * rs + ((((d0 >> 3)) ^ (row & 7)) << 4) + ((d0 & 4) << 1);
    *reinterpret_cast<uint2*>(p)      = make_uint2(h01, h23);
    *reinterpret_cast<uint2*>(p + pg) = make_uint2(l01, l23);
}

__global__ void __launch_bounds__(NT, 1)
interaction_ldm_kernel(const float* __restrict__ h1g, const float* __restrict__ h2g,
                       const float* __restrict__ gam, const float* __restrict__ bet,
                       float* __restrict__ out)
{
    extern __shared__ char smc[];
    const u32 ub = smem_u32(smc);
    float2* scr = reinterpret_cast<float2*>(smc);    // LN scratch overlays h1 (dead then)

    const int tid  = threadIdx.x;
    const int lane = tid & 31;
    const int wid  = tid >> 5;        // 0..15
    const int lq   = lane >> 2;
    const int lr   = lane & 3;
    const int g    = blockIdx.x;

    const float4* h1v = reinterpret_cast<const float4*>(h1g) + (size_t)g * 4096;
    const float4* h2v = reinterpret_cast<const float4*>(h2g) + (size_t)g * 8192;
    float4* o1x = reinterpret_cast<float4*>(out) + (size_t)g * 8192;
    float4* o2x = reinterpret_cast<float4*>(out) + (size_t)NB * 8192 + (size_t)g * 16384;
    float* o1 = out + (size_t)g * 32768;
    float* o2 = out + (size_t)NB * 32768 + (size_t)g * 65536;

    // ---------------- Phase 1a: load d<128 halves, copy-out, split to planes --------------
    #pragma unroll
    for (int it = 0; it < 4; ++it) {                  // h1 d<128: 2048 f4
        int idx = it * NT + tid, row = idx >> 5, c4 = idx & 31;
        float4 v = h1v[row * 64 + c4];
        o1x[(size_t)row * 128 + c4] = v;
        plane_st(smc + H1O, row, c4 << 2, 1024, 512, v);
    }
    #pragma unroll
    for (int it = 0; it < 8; ++it) {                  // h2 d<128: 4096 f4
        int idx = it * NT + tid, row = idx >> 5, c4 = idx & 31;
        float4 v = h2v[row * 64 + c4];
        o2x[(size_t)row * 128 + c4] = v;
        plane_st(smc + H2O, row, c4 << 2, 1024, 512, v);
    }
    // prefetch d>=128 halves into registers (LDGs in flight across the barrier)
    float4 p1[4], p2[8];
    #pragma unroll
    for (int it = 0; it < 4; ++it) {
        int idx = it * NT + tid;
        p1[it] = h1v[(idx >> 5) * 64 + 32 + (idx & 31)];
    }
    #pragma unroll
    for (int it = 0; it < 8; ++it) {
        int idx = it * NT + tid;
        p2[it] = h2v[(idx >> 5) * 64 + 32 + (idx & 31)];
    }
    __syncthreads();

    // ================ GEMM1: I[64,128] = clip(scale * h1 @ h2^T), K=256 ===================
    {
        const int m0 = (wid & 3) * 16;
        const int nq = wid >> 2;
        float c[4][4];
        #pragma unroll
        for (int j = 0; j < 4; ++j)
            #pragma unroll
            for (int i = 0; i < 4; ++i) c[j][i] = 0.f;

        const u32 lxor  = (u32)(lane & 7);
        const u32 arowb = ub + H1O + (u32)(m0 + (lane & 15)) * 1024u;
        const u32 browb0 = ub + H2O + (u32)(nq * 32 + ((lane >> 4) << 3) + (lane & 7)) * 1024u;
        const u32 browb1 = browb0 + 16384u;

        // ---- K half 1 (d < 128) while prefetch LDGs fly ----
        #pragma unroll 2
        for (int k = 0; k < 8; ++k) {
            u32 aaddr = arowb + (((2u * k + (lane >> 4)) ^ lxor) << 4);
            u32 aH[4], aL[4];
            ldm4(aH, aaddr);
            ldm4(aL, aaddr + 512);
            u32 cb = ((2u * k + ((lane >> 3) & 1)) ^ lxor) << 4;
            u32 bH0[4], bL0[4], bH1[4], bL1[4];
            ldm4(bH0, browb0 + cb);
            ldm4(bL0, browb0 + cb + 512);
            ldm4(bH1, browb1 + cb);
            ldm4(bL1, browb1 + cb + 512);
            mma3(c[0], aH, aL, bH0, bL0);
            mma3(c[1], aH, aL, bH0 + 2, bL0 + 2);
            mma3(c[2], aH, aL, bH1, bL1);
            mma3(c[3], aH, aL, bH1 + 2, bL1 + 2);
        }

        // ---- Phase 1b: store prefetched d>=128 halves ----
        #pragma unroll
        for (int it = 0; it < 4; ++it) {
            int idx = it * NT + tid, row = idx >> 5, c4 = 32 + (idx & 31);
            o1x[(size_t)row * 128 + c4] = p1[it];
            plane_st(smc + H1O, row, c4 << 2, 1024, 512, p1[it]);
        }
        #pragma unroll
        for (int it = 0; it < 8; ++it) {
            int idx = it * NT + tid, row = idx >> 5, c4 = 32 + (idx & 31);
            o2x[(size_t)row * 128 + c4] = p2[it];
            plane_st(smc + H2O, row, c4 << 2, 1024, 512, p2[it]);
        }
        __syncthreads();

        // ---- K half 2 (d >= 128) ----
        #pragma unroll 2
        for (int k = 8; k < 16; ++k) {
            u32 aaddr = arowb + (((2u * k + (lane >> 4)) ^ lxor) << 4);
            u32 aH[4], aL[4];
            ldm4(aH, aaddr);
            ldm4(aL, aaddr + 512);
            u32 cb = ((2u * k + ((lane >> 3) & 1)) ^ lxor) << 4;
            u32 bH0[4], bL0[4], bH1[4], bL1[4];
            ldm4(bH0, browb0 + cb);
            ldm4(bL0, browb0 + cb + 512);
            ldm4(bH1, browb1 + cb);
            ldm4(bL1, browb1 + cb + 512);
            mma3(c[0], aH, aL, bH0, bL0);
            mma3(c[1], aH, aL, bH0 + 2, bL0 + 2);
            mma3(c[2], aH, aL, bH1, bL1);
            mma3(c[3], aH, aL, bH1 + 2, bL1 + 2);
        }

        // epilogue: scale+clip, split, store to I planes (rows r and r+8)
        const int r = m0 + lq;
        #pragma unroll
        for (int j = 0; j < 4; ++j) {
            const int nc = nq * 32 + j * 8 + lr * 2;
            float v0 = fminf(fmaxf(c[j][0] * ISCALE, -10.f), 10.f);
            float v1 = fminf(fmaxf(c[j][1] * ISCALE, -10.f), 10.f);
            float v2 = fminf(fmaxf(c[j][2] * ISCALE, -10.f), 10.f);
            float v3 = fminf(fmaxf(c[j][3] * ISCALE, -10.f), 10.f);
            u32 h01, l01, h23, l23;
            split2(v0, v1, h01, l01);
            split2(v2, v3, h23, l23);
            char* p0 = smc + IRO + (r << 9) + (((nc >> 3) ^ (r & 7)) << 4) + ((nc & 7) << 1);
            *reinterpret_cast<u32*>(p0)              = h01;
            *reinterpret_cast<u32*>(p0 + 256)        = l01;
            *reinterpret_cast<u32*>(p0 + 4096)       = h23;
            *reinterpret_cast<u32*>(p0 + 4096 + 256) = l23;
        }
    }
    __syncthreads();

    // ======== Fused GEMM3 + GEMM2 mainloops (independent given I; no barrier between) =====
    // G3: C3[128,256] = I^T @ h1 (K=64). warp: m16 = (wid&7)*16, n128 half = wid>>3.
    // G2: C2[64,256]  = I @ h2  (K=128). warp: m16 = (wid&3)*16, n64 quarter = wid>>2.
    const int mp0 = (wid & 7) * 16;
    const int nh  = wid >> 3;
    const int m0g2 = (wid & 3) * 16;
    const int nq2  = wid >> 2;
    float c3[16][4];
    float c2[8][4];
    {
        #pragma unroll
        for (int j = 0; j < 16; ++j)
            #pragma unroll
            for (int i = 0; i < 4; ++i) c3[j][i] = 0.f;
        #pragma unroll
        for (int j = 0; j < 8; ++j)
            #pragma unroll
            for (int i = 0; i < 4; ++i) c2[j][i] = 0.f;

        const u32 lxor = (u32)(lane & 7);
        // ---- G3 mma loop ----
        {
            const u32 abase = ub + IRO + ((((u32)(mp0 >> 3) + ((lane >> 3) & 1)) ^ lxor) << 4);
            const int arofs = (lane & 7) + ((lane & 16) >> 1);
            const int brofs = (lane & 7) + (lane & 8);
            #pragma unroll 1
            for (int k = 0; k < 4; ++k) {
                const int k0 = 16 * k;
                u32 aaddr = abase + (u32)(k0 + arofs) * 512u;
                u32 aH[4], aL[4];
                ldm4t(aH, aaddr);
                ldm4t(aL, aaddr + 256);
                u32 bro = ub + H1O + (u32)(k0 + brofs) * 1024u;
                #pragma unroll
                for (int jj = 0; jj < 8; ++jj) {
                    u32 baddr = bro + (((u32)(nh * 16 + 2 * jj + (lane >> 4)) ^ lxor) << 4);
                    u32 bH[4], bL[4];
                    ldm4t(bH, baddr);
                    ldm4t(bL, baddr + 512);
                    mma3(c3[2 * jj],     aH, aL, bH, bL);
                    mma3(c3[2 * jj + 1], aH, aL, bH + 2, bL + 2);
                }
            }
        }
        // ---- G2 mma loop (no barrier: reads I + h2 planes, both still valid) ----
        {
            const u32 arowb = ub + IRO + (u32)(m0g2 + (lane & 15)) * 512u;
            const int brofs = (lane & 7) + (lane & 8);
            #pragma unroll 1
            for (int k = 0; k < 8; ++k) {
                u32 aaddr = arowb + (((2u * k + (lane >> 4)) ^ lxor) << 4);
                u32 aH[4], aL[4];
                ldm4(aH, aaddr);
                ldm4(aL, aaddr + 256);
                u32 bro = ub + H2O + (u32)(16 * k + brofs) * 1024u;
                #pragma unroll
                for (int jj = 0; jj < 4; ++jj) {
                    u32 baddr = bro + (((u32)(nq2 * 8 + 2 * jj + (lane >> 4)) ^ lxor) << 4);
                    u32 bH[4], bL[4];
                    ldm4t(bH, baddr);
                    ldm4t(bL, baddr + 512);
                    mma3(c2[2 * jj],     aH, aL, bH, bL);
                    mma3(c2[2 * jj + 1], aH, aL, bH + 2, bL + 2);
                }
            }
        }
    }
    __syncthreads();                          // all plane reads done -> scratch reuse OK

    // ---- LN partial writes: G3 -> scr[0..255], G2 -> scr[256..511] ----
    {
        const int r3 = mp0 + lq;
        float s0 = 0.f, q0 = 0.f, s1 = 0.f, q1 = 0.f;
        #pragma unroll
        for (int j = 0; j < 16; ++j) {
            s0 += c3[j][0] + c3[j][1];  q0 += c3[j][0] * c3[j][0] + c3[j][1] * c3[j][1];
            s1 += c3[j][2] + c3[j][3];  q1 += c3[j][2] * c3[j][2] + c3[j][3] * c3[j][3];
        }
        #pragma unroll
        for (int o = 1; o <= 2; o <<= 1) {
            s0 += __shfl_xor_sync(0xffffffffu, s0, o);
            q0 += __shfl_xor_sync(0xffffffffu, q0, o);
            s1 += __shfl_xor_sync(0xffffffffu, s1, o);
            q1 += __shfl_xor_sync(0xffffffffu, q1, o);
        }
        float t0 = 0.f, u0 = 0.f, t1 = 0.f, u1 = 0.f;
        #pragma unroll
        for (int j = 0; j < 8; ++j) {
            t0 += c2[j][0] + c2[j][1];  u0 += c2[j][0] * c2[j][0] + c2[j][1] * c2[j][1];
            t1 += c2[j][2] + c2[j][3];  u1 += c2[j][2] * c2[j][2] + c2[j][3] * c2[j][3];
        }
        #pragma unroll
        for (int o = 1; o <= 2; o <<= 1) {
            t0 += __shfl_xor_sync(0xffffffffu, t0, o);
            u0 += __shfl_xor_sync(0xffffffffu, u0, o);
            t1 += __shfl_xor_sync(0xffffffffu, t1, o);
            u1 += __shfl_xor_sync(0xffffffffu, u1, o);
        }
        if (lr == 0) {
            scr[r3 * 2 + nh]       = make_float2(s0, q0);
            scr[(r3 + 8) * 2 + nh] = make_float2(s1, q1);
            const int r2 = m0g2 + lq;
            scr[256 + r2 * 4 + nq2]       = make_float2(t0, u0);
            scr[256 + (r2 + 8) * 4 + nq2] = make_float2(t1, u1);
        }
    }
    __syncthreads();

    // ---- LN compute + store: G3 -> h2_enh[:,256:512] ----
    {
        const int r = mp0 + lq;
        float2 pa = scr[r * 2], pb = scr[r * 2 + 1];
        float2 pc = scr[(r + 8) * 2], pd = scr[(r + 8) * 2 + 1];
        float mu0 = (pa.x + pb.x) * (1.f / 256.f);
        float iv0 = rsqrtf((pa.y + pb.y) * (1.f / 256.f) - mu0 * mu0 + LN_EPS);
        float mu1 = (pc.x + pd.x) * (1.f / 256.f);
        float iv1 = rsqrtf((pc.y + pd.y) * (1.f / 256.f) - mu1 * mu1 + LN_EPS);
        #pragma unroll
        for (int j = 0; j < 16; ++j) {
            const int nc = nh * 128 + j * 8 + lr * 2;
            float2 gm = *reinterpret_cast<const float2*>(gam + nc);
            float2 bt = *reinterpret_cast<const float2*>(bet + nc);
            float2 u0 = make_float2((c3[j][0] - mu0) * iv0 * gm.x + bt.x,
                                    (c3[j][1] - mu0) * iv0 * gm.y + bt.y);
            float2 u1 = make_float2((c3[j][2] - mu1) * iv1 * gm.x + bt.x,
                                    (c3[j][3] - mu1) * iv1 * gm.y + bt.y);
            *reinterpret_cast<float2*>(o2 + (size_t)r * 512 + 256 + nc)       = u0;
            *reinterpret_cast<float2*>(o2 + (size_t)(r + 8) * 512 + 256 + nc) = u1;
        }
    }
    // ---- LN compute + store: G2 -> h1_enh[:,256:512] ----
    {
        const int r = m0g2 + lq;
        float S0 = 0.f, Q0 = 0.f, S1 = 0.f, Q1 = 0.f;
        #pragma unroll
        for (int q = 0; q < 4; ++q) {
            float2 p0 = scr[256 + r * 4 + q];       S0 += p0.x; Q0 += p0.y;
            float2 p1 = scr[256 + (r + 8) * 4 + q]; S1 += p1.x; Q1 += p1.y;
        }
        float mu0 = S0 * (1.f / 256.f);
        float iv0 = rsqrtf(Q0 * (1.f / 256.f) - mu0 * mu0 + LN_EPS);
        float mu1 = S1 * (1.f / 256.f);
        float iv1 = rsqrtf(Q1 * (1.f / 256.f) - mu1 * mu1 + LN_EPS);
        #pragma unroll
        for (int j = 0; j < 8; ++j) {
            const int nc = nq2 * 64 + j * 8 + lr * 2;
            float2 gm = *reinterpret_cast<const float2*>(gam + nc);
            float2 bt = *reinterpret_cast<const float2*>(bet + nc);
            float2 u0 = make_float2((c2[j][0] - mu0) * iv0 * gm.x + bt.x,
                                    (c2[j][1] - mu0) * iv0 * gm.y + bt.y);
            float2 u1 = make_float2((c2[j][2] - mu1) * iv1 * gm.x + bt.x,
                                    (c2[j][3] - mu1) * iv1 * gm.y + bt.y);
            *reinterpret_cast<float2*>(o1 + (size_t)r * 512 + 256 + nc)       = u0;
            *reinterpret_cast<float2*>(o1 + (size_t)(r + 8) * 512 + 256 + nc) = u1;
        }
    }
}

extern "C" void kernel_launch(void* const* d_in, const int* in_sizes, int n_in,
                              void* d_out, int out_size)
{
    const float* h1  = (const float*)d_in[0];
    const float* h2  = (const float*)d_in[1];
    const float* gam = (const float*)d_in[4];
    const float* bet = (const float*)d_in[5];
    float* out = (float*)d_out;

    cudaFuncSetAttribute(interaction_ldm_kernel,
                         cudaFuncAttributeMaxDynamicSharedMemorySize, SMEM_BYTES);
    interaction_ldm_kernel<<<NB, NT, SMEM_BYTES>>>(h1, h2, gam, bet, out);
}

// round 16
// speedup vs baseline: 1.2978x; 1.2978x over previous
#include <cuda_runtime.h>
#include <cuda_fp16.h>
#include <cstdint>

typedef unsigned int u32;

#define NB 1024
#define LN_EPS 1e-5f
#define ISCALE 0.0625f
#define NT 512

// SMEM byte offsets. fp16 planes, 16B chunks swizzled by (chunk ^ (row & 7)).
// h1: hi+lo (A in G1, B-hi in G3). h2: hi ONLY (B in G1,G2). I: hi+lo (A in G2,G3).
#define H1O 0          // 64 rows x 1024B (hi 512 | lo 512)
#define H2O 65536      // 128 rows x 512B (hi only)
#define IRO 131072     // 64 rows x 512B (hi 256 | lo 256)
#define SMEM_BYTES 163840

__device__ __forceinline__ u32 smem_u32(const void* p) {
    u32 a;
    asm("{ .reg .u64 t; cvta.to.shared.u64 t, %1; cvt.u32.u64 %0, t; }" : "=r"(a) : "l"(p));
    return a;
}
// fp16 pair pack (x -> low 16 bits)
__device__ __forceinline__ u32 pack2h(float x, float y) {
    u32 hp;
    asm("cvt.rn.f16x2.f32 %0, %1, %2;" : "=r"(hp) : "f"(y), "f"(x));
    return hp;
}
// split float pair into packed-fp16 hi and lo (lo = x - fp16(x))
__device__ __forceinline__ void split2(float x, float y, u32& hp, u32& lp) {
    hp = pack2h(x, y);
    __half2 h = *reinterpret_cast<__half2*>(&hp);
    float2 hf = __half22float2(h);
    lp = pack2h(x - hf.x, y - hf.y);
}
__device__ __forceinline__ void mma16816(float* c, const u32* a, const u32* b) {
    asm volatile(
        "mma.sync.aligned.m16n8k16.row.col.f32.f16.f16.f32 "
        "{%0,%1,%2,%3}, {%4,%5,%6,%7}, {%8,%9}, {%0,%1,%2,%3};"
        : "+f"(c[0]), "+f"(c[1]), "+f"(c[2]), "+f"(c[3])
        : "r"(a[0]), "r"(a[1]), "r"(a[2]), "r"(a[3]), "r"(b[0]), "r"(b[1]));
}
// 2-term fp16 split product: AhiBhi + AloBhi  (B uses hi plane only)
__device__ __forceinline__ void mma2(float* c, const u32* aH, const u32* aL, const u32* bH) {
    mma16816(c, aH, bH);
    mma16816(c, aL, bH);
}
__device__ __forceinline__ void ldm4(u32* r, u32 a) {
    asm volatile("ldmatrix.sync.aligned.m8n8.x4.shared.b16 {%0,%1,%2,%3}, [%4];"
        : "=r"(r[0]), "=r"(r[1]), "=r"(r[2]), "=r"(r[3]) : "r"(a));
}
__device__ __forceinline__ void ldm4t(u32* r, u32 a) {
    asm volatile("ldmatrix.sync.aligned.m8n8.x4.trans.shared.b16 {%0,%1,%2,%3}, [%4];"
        : "=r"(r[0]), "=r"(r[1]), "=r"(r[2]), "=r"(r[3]) : "r"(a));
}
// store one float4 as split hi/lo fp16 planes at (row, d0); row stride rs bytes, plane gap pg
__device__ __forceinline__ void plane_st(char* bp, int row, int d0, int rs, int pg, float4 v) {
    u32 h01, l01, h23, l23;
    split2(v.x, v.y, h01, l01);
    split2(v.z, v.w, h23, l23);
    char* p = bp + row * rs + ((((d0 >> 3)) ^ (row & 7)) << 4) + ((d0 & 4) << 1);
    *reinterpret_cast<uint2*>(p)      = make_uint2(h01, h23);
    *reinterpret_cast<uint2*>(p + pg) = make_uint2(l01, l23);
}
// hi-only store (h2)
__device__ __forceinline__ void plane_st_hi(char* bp, int row, int d0, int rs, float4 v) {
    u32 h01 = pack2h(v.x, v.y), h23 = pack2h(v.z, v.w);
    char* p = bp + row * rs + ((((d0 >> 3)) ^ (row & 7)) << 4) + ((d0 & 4) << 1);
    *reinterpret_cast<uint2*>(p) = make_uint2(h01, h23);
}

__global__ void __launch_bounds__(NT, 1)
interaction_ldm_kernel(const float* __restrict__ h1g, const float* __restrict__ h2g,
                       const float* __restrict__ gam, const float* __restrict__ bet,
                       float* __restrict__ out)
{
    extern __shared__ char smc[];
    const u32 ub = smem_u32(smc);
    float2* scr = reinterpret_cast<float2*>(smc);    // LN scratch overlays h1 (dead then)

    const int tid  = threadIdx.x;
    const int lane = tid & 31;
    const int wid  = tid >> 5;        // 0..15
    const int lq   = lane >> 2;
    const int lr   = lane & 3;
    const int g    = blockIdx.x;

    const float4* h1v = reinterpret_cast<const float4*>(h1g) + (size_t)g * 4096;
    const float4* h2v = reinterpret_cast<const float4*>(h2g) + (size_t)g * 8192;
    float4* o1x = reinterpret_cast<float4*>(out) + (size_t)g * 8192;
    float4* o2x = reinterpret_cast<float4*>(out) + (size_t)NB * 8192 + (size_t)g * 16384;
    float* o1 = out + (size_t)g * 32768;
    float* o2 = out + (size_t)NB * 32768 + (size_t)g * 65536;

    // ---------------- Phase 1a: load d<128 halves, copy-out, split to planes --------------
    #pragma unroll
    for (int it = 0; it < 4; ++it) {                  // h1 d<128
        int idx = it * NT + tid, row = idx >> 5, c4 = idx & 31;
        float4 v = h1v[row * 64 + c4];
        o1x[(size_t)row * 128 + c4] = v;
        plane_st(smc + H1O, row, c4 << 2, 1024, 512, v);
    }
    #pragma unroll
    for (int it = 0; it < 8; ++it) {                  // h2 d<128 (hi only)
        int idx = it * NT + tid, row = idx >> 5, c4 = idx & 31;
        float4 v = h2v[row * 64 + c4];
        o2x[(size_t)row * 128 + c4] = v;
        plane_st_hi(smc + H2O, row, c4 << 2, 512, v);
    }
    // prefetch d>=128 halves into registers (LDGs in flight across the barrier)
    float4 p1[4], p2[8];
    #pragma unroll
    for (int it = 0; it < 4; ++it) {
        int idx = it * NT + tid;
        p1[it] = h1v[(idx >> 5) * 64 + 32 + (idx & 31)];
    }
    #pragma unroll
    for (int it = 0; it < 8; ++it) {
        int idx = it * NT + tid;
        p2[it] = h2v[(idx >> 5) * 64 + 32 + (idx & 31)];
    }
    __syncthreads();

    // ================ GEMM1: I[64,128] = clip(scale * h1 @ h2^T), K=256 ===================
    // warp: m16 = (wid&3)*16, n32 = (wid>>2)*32 (two paired-B 16-row tiles)
    {
        const int m0 = (wid & 3) * 16;
        const int nq = wid >> 2;
        float c[4][4];
        #pragma unroll
        for (int j = 0; j < 4; ++j)
            #pragma unroll
            for (int i = 0; i < 4; ++i) c[j][i] = 0.f;

        const u32 lxor  = (u32)(lane & 7);
        const u32 arowb = ub + H1O + (u32)(m0 + (lane & 15)) * 1024u;
        const u32 browb0 = ub + H2O + (u32)(nq * 32 + ((lane >> 4) << 3) + (lane & 7)) * 512u;
        const u32 browb1 = browb0 + 8192u;

        // ---- K half 1 (d < 128) while prefetch LDGs fly ----
        #pragma unroll 2
        for (int k = 0; k < 8; ++k) {
            u32 aaddr = arowb + (((2u * k + (lane >> 4)) ^ lxor) << 4);
            u32 aH[4], aL[4];
            ldm4(aH, aaddr);
            ldm4(aL, aaddr + 512);
            u32 cb = ((2u * k + ((lane >> 3) & 1)) ^ lxor) << 4;
            u32 bH0[4], bH1[4];
            ldm4(bH0, browb0 + cb);
            ldm4(bH1, browb1 + cb);
            mma2(c[0], aH, aL, bH0);
            mma2(c[1], aH, aL, bH0 + 2);
            mma2(c[2], aH, aL, bH1);
            mma2(c[3], aH, aL, bH1 + 2);
        }

        // ---- Phase 1b: store prefetched d>=128 halves ----
        #pragma unroll
        for (int it = 0; it < 4; ++it) {
            int idx = it * NT + tid, row = idx >> 5, c4 = 32 + (idx & 31);
            o1x[(size_t)row * 128 + c4] = p1[it];
            plane_st(smc + H1O, row, c4 << 2, 1024, 512, p1[it]);
        }
        #pragma unroll
        for (int it = 0; it < 8; ++it) {
            int idx = it * NT + tid, row = idx >> 5, c4 = 32 + (idx & 31);
            o2x[(size_t)row * 128 + c4] = p2[it];
            plane_st_hi(smc + H2O, row, c4 << 2, 512, p2[it]);
        }
        __syncthreads();

        // ---- K half 2 (d >= 128) ----
        #pragma unroll 2
        for (int k = 8; k < 16; ++k) {
            u32 aaddr = arowb + (((2u * k + (lane >> 4)) ^ lxor) << 4);
            u32 aH[4], aL[4];
            ldm4(aH, aaddr);
            ldm4(aL, aaddr + 512);
            u32 cb = ((2u * k + ((lane >> 3) & 1)) ^ lxor) << 4;
            u32 bH0[4], bH1[4];
            ldm4(bH0, browb0 + cb);
            ldm4(bH1, browb1 + cb);
            mma2(c[0], aH, aL, bH0);
            mma2(c[1], aH, aL, bH0 + 2);
            mma2(c[2], aH, aL, bH1);
            mma2(c[3], aH, aL, bH1 + 2);
        }

        // epilogue: scale+clip, split, store to I planes (rows r and r+8)
        const int r = m0 + lq;
        #pragma unroll
        for (int j = 0; j < 4; ++j) {
            const int nc = nq * 32 + j * 8 + lr * 2;
            float v0 = fminf(fmaxf(c[j][0] * ISCALE, -10.f), 10.f);
            float v1 = fminf(fmaxf(c[j][1] * ISCALE, -10.f), 10.f);
            float v2 = fminf(fmaxf(c[j][2] * ISCALE, -10.f), 10.f);
            float v3 = fminf(fmaxf(c[j][3] * ISCALE, -10.f), 10.f);
            u32 h01, l01, h23, l23;
            split2(v0, v1, h01, l01);
            split2(v2, v3, h23, l23);
            char* p0 = smc + IRO + (r << 9) + (((nc >> 3) ^ (r & 7)) << 4) + ((nc & 7) << 1);
            *reinterpret_cast<u32*>(p0)              = h01;
            *reinterpret_cast<u32*>(p0 + 256)        = l01;
            *reinterpret_cast<u32*>(p0 + 4096)       = h23;
            *reinterpret_cast<u32*>(p0 + 4096 + 256) = l23;
        }
    }
    __syncthreads();

    // ================ GEMM3: C3[128,256] = I^T @ h1, K=64 =================================
    // warp: m16 = (wid&7)*16, n128 half = wid>>3; B = h1 hi plane only
    {
        const int mp0 = (wid & 7) * 16;
        const int nh  = wid >> 3;
        float c[16][4];
        #pragma unroll
        for (int j = 0; j < 16; ++j)
            #pragma unroll
            for (int i = 0; i < 4; ++i) c[j][i] = 0.f;

        const u32 lxor  = (u32)(lane & 7);
        const u32 abase = ub + IRO + ((((u32)(mp0 >> 3) + ((lane >> 3) & 1)) ^ lxor) << 4);
        const int arofs = (lane & 7) + ((lane & 16) >> 1);
        const int brofs = (lane & 7) + (lane & 8);

        #pragma unroll 1
        for (int k = 0; k < 4; ++k) {
            const int k0 = 16 * k;
            u32 aaddr = abase + (u32)(k0 + arofs) * 512u;
            u32 aH[4], aL[4];
            ldm4t(aH, aaddr);
            ldm4t(aL, aaddr + 256);
            u32 bro = ub + H1O + (u32)(k0 + brofs) * 1024u;
            #pragma unroll
            for (int jj = 0; jj < 8; ++jj) {
                u32 baddr = bro + (((u32)(nh * 16 + 2 * jj + (lane >> 4)) ^ lxor) << 4);
                u32 bH[4];
                ldm4t(bH, baddr);
                mma2(c[2 * jj],     aH, aL, bH);
                mma2(c[2 * jj + 1], aH, aL, bH + 2);
            }
        }
        __syncthreads();                      // h1 planes dead -> scratch reuse OK
        const int r = mp0 + lq;
        float s0 = 0.f, q0 = 0.f, s1 = 0.f, q1 = 0.f;
        #pragma unroll
        for (int j = 0; j < 16; ++j) {
            s0 += c[j][0] + c[j][1];  q0 += c[j][0] * c[j][0] + c[j][1] * c[j][1];
            s1 += c[j][2] + c[j][3];  q1 += c[j][2] * c[j][2] + c[j][3] * c[j][3];
        }
        #pragma unroll
        for (int o = 1; o <= 2; o <<= 1) {
            s0 += __shfl_xor_sync(0xffffffffu, s0, o);
            q0 += __shfl_xor_sync(0xffffffffu, q0, o);
            s1 += __shfl_xor_sync(0xffffffffu, s1, o);
            q1 += __shfl_xor_sync(0xffffffffu, q1, o);
        }
        if (lr == 0) {
            scr[r * 2 + nh]       = make_float2(s0, q0);
            scr[(r + 8) * 2 + nh] = make_float2(s1, q1);
        }
        __syncthreads();
        float2 pa = scr[r * 2], pb = scr[r * 2 + 1];
        float2 pc = scr[(r + 8) * 2], pd = scr[(r + 8) * 2 + 1];
        float mu0 = (pa.x + pb.x) * (1.f / 256.f);
        float iv0 = rsqrtf((pa.y + pb.y) * (1.f / 256.f) - mu0 * mu0 + LN_EPS);
        float mu1 = (pc.x + pd.x) * (1.f / 256.f);
        float iv1 = rsqrtf((pc.y + pd.y) * (1.f / 256.f) - mu1 * mu1 + LN_EPS);
        #pragma unroll
        for (int j = 0; j < 16; ++j) {
            const int nc = nh * 128 + j * 8 + lr * 2;
            float2 gm = *reinterpret_cast<const float2*>(gam + nc);
            float2 bt = *reinterpret_cast<const float2*>(bet + nc);
            float2 u0 = make_float2((c[j][0] - mu0) * iv0 * gm.x + bt.x,
                                    (c[j][1] - mu0) * iv0 * gm.y + bt.y);
            float2 u1 = make_float2((c[j][2] - mu1) * iv1 * gm.x + bt.x,
                                    (c[j][3] - mu1) * iv1 * gm.y + bt.y);
            *reinterpret_cast<float2*>(o2 + (size_t)r * 512 + 256 + nc)       = u0;
            *reinterpret_cast<float2*>(o2 + (size_t)(r + 8) * 512 + 256 + nc) = u1;
        }
    }

    // ================ GEMM2: C2[64,256] = I @ h2, K=128 ===================================
    // warp: m16 = (wid&3)*16, n64 quarter = wid>>2; B = h2 hi plane only
    {
        const int m0 = (wid & 3) * 16;
        const int nq = wid >> 2;
        float c[8][4];
        #pragma unroll
        for (int j = 0; j < 8; ++j)
            #pragma unroll
            for (int i = 0; i < 4; ++i) c[j][i] = 0.f;

        const u32 lxor  = (u32)(lane & 7);
        const u32 arowb = ub + IRO + (u32)(m0 + (lane & 15)) * 512u;
        const int brofs = (lane & 7) + (lane & 8);

        #pragma unroll 1
        for (int k = 0; k < 8; ++k) {
            u32 aaddr = arowb + (((2u * k + (lane >> 4)) ^ lxor) << 4);
            u32 aH[4], aL[4];
            ldm4(aH, aaddr);
            ldm4(aL, aaddr + 256);
            u32 bro = ub + H2O + (u32)(16 * k + brofs) * 512u;
            #pragma unroll
            for (int jj = 0; jj < 4; ++jj) {
                u32 baddr = bro + (((u32)(nq * 8 + 2 * jj + (lane >> 4)) ^ lxor) << 4);
                u32 bH[4];
                ldm4t(bH, baddr);
                mma2(c[2 * jj],     aH, aL, bH);
                mma2(c[2 * jj + 1], aH, aL, bH + 2);
            }
        }
        __syncthreads();                      // orders prior scratch reads before reuse
        const int r = m0 + lq;
        float s0 = 0.f, q0 = 0.f, s1 = 0.f, q1 = 0.f;
        #pragma unroll
        for (int j = 0; j < 8; ++j) {
            s0 += c[j][0] + c[j][1];  q0 += c[j][0] * c[j][0] + c[j][1] * c[j][1];
            s1 += c[j][2] + c[j][3];  q1 += c[j][2] * c[j][2] + c[j][3] * c[j][3];
        }
        #pragma unroll
        for (int o = 1; o <= 2; o <<= 1) {
            s0 += __shfl_xor_sync(0xffffffffu, s0, o);
            q0 += __shfl_xor_sync(0xffffffffu, q0, o);
            s1 += __shfl_xor_sync(0xffffffffu, s1, o);
            q1 += __shfl_xor_sync(0xffffffffu, q1, o);
        }
        if (lr == 0) {
            scr[r * 4 + nq]       = make_float2(s0, q0);
            scr[(r + 8) * 4 + nq] = make_float2(s1, q1);
        }
        __syncthreads();
        float S0 = 0.f, Q0 = 0.f, S1 = 0.f, Q1 = 0.f;
        #pragma unroll
        for (int q = 0; q < 4; ++q) {
            float2 p0 = scr[r * 4 + q];       S0 += p0.x; Q0 += p0.y;
            float2 p1 = scr[(r + 8) * 4 + q]; S1 += p1.x; Q1 += p1.y;
        }
        float mu0 = S0 * (1.f / 256.f);
        float iv0 = rsqrtf(Q0 * (1.f / 256.f) - mu0 * mu0 + LN_EPS);
        float mu1 = S1 * (1.f / 256.f);
        float iv1 = rsqrtf(Q1 * (1.f / 256.f) - mu1 * mu1 + LN_EPS);
        #pragma unroll
        for (int j = 0; j < 8; ++j) {
            const int nc = nq * 64 + j * 8 + lr * 2;
            float2 gm = *reinterpret_cast<const float2*>(gam + nc);
            float2 bt = *reinterpret_cast<const float2*>(bet + nc);
            float2 u0 = make_float2((c[j][0] - mu0) * iv0 * gm.x + bt.x,
                                    (c[j][1] - mu0) * iv0 * gm.y + bt.y);
            float2 u1 = make_float2((c[j][2] - mu1) * iv1 * gm.x + bt.x,
                                    (c[j][3] - mu1) * iv1 * gm.y + bt.y);
            *reinterpret_cast<float2*>(o1 + (size_t)r * 512 + 256 + nc)       = u0;
            *reinterpret_cast<float2*>(o1 + (size_t)(r + 8) * 512 + 256 + nc) = u1;
        }
    }
}

extern "C" void kernel_launch(void* const* d_in, const int* in_sizes, int n_in,
                              void* d_out, int out_size)
{
    const float* h1  = (const float*)d_in[0];
    const float* h2  = (const float*)d_in[1];
    const float* gam = (const float*)d_in[4];
    const float* bet = (const float*)d_in[5];
    float* out = (float*)d_out;

    cudaFuncSetAttribute(interaction_ldm_kernel,
                         cudaFuncAttributeMaxDynamicSharedMemorySize, SMEM_BYTES);
    interaction_ldm_kernel<<<NB, NT, SMEM_BYTES>>>(h1, h2, gam, bet, out);
}